// round 11
// baseline (speedup 1.0000x reference)
#include <cuda_runtime.h>
#include <cstdint>
#include <cstddef>

// ---------------------------------------------------------------------------
// Scratch (device globals — no allocation allowed)
// ---------------------------------------------------------------------------
__device__ float g_noise[(size_t)1024 * 131072];   // 512 MiB prescaled gumbel noise
__device__ float g_h1[64 * 8192];
__device__ float g_h2[64 * 8192];
__device__ float g_mask0[64 * 2048];
__device__ float g_p [(size_t)8 * 64 * 8192];      // K-split partials (g1 x4 / g2 x8)
__device__ float g_p3[(size_t)8 * 64 * 2048];      // gemm3 x8 partials
__device__ uint2 g_keys[1024];
__device__ int   g_icnt[1024];                     // per-iteration noise arrivals

// ---------------------------------------------------------------------------
// Threefry-2x32-20 (bit-exact JAX)
// ---------------------------------------------------------------------------
__device__ __forceinline__ void tf_block(uint32_t ks0, uint32_t ks1, uint32_t ks2,
                                         uint32_t x0, uint32_t x1,
                                         uint32_t& o0, uint32_t& o1)
{
    x0 += ks0; x1 += ks1;
#define TFR(r) { x0 += x1; x1 = __funnelshift_l(x1, x1, (r)); x1 ^= x0; }
    TFR(13); TFR(15); TFR(26); TFR(6);
    x0 += ks1; x1 += ks2 + 1u;
    TFR(17); TFR(29); TFR(16); TFR(24);
    x0 += ks2; x1 += ks0 + 2u;
    TFR(13); TFR(15); TFR(26); TFR(6);
    x0 += ks0; x1 += ks1 + 3u;
    TFR(17); TFR(29); TFR(16); TFR(24);
    x0 += ks1; x1 += ks2 + 4u;
    TFR(13); TFR(15); TFR(26); TFR(6);
    x0 += ks2; x1 += ks0 + 5u;
#undef TFR
    o0 = x0; o1 = x1;
}

// per-replay init: reset counters + fold per-iteration keys
__global__ void keys_kernel()
{
    int i = threadIdx.x;
    g_icnt[i] = 0;
    uint32_t o0, o1;
    tf_block(0u, 42u, 0u ^ 42u ^ 0x1BD11BDAu, 0u, (uint32_t)i, o0, o1);
    g_keys[i] = make_uint2(o0, o1);
}

// bits -> n = -2*log2(-ln u)  so the iter loop is e = 2^(mask*C + n), C = 2*log2(e)
__device__ __forceinline__ float bits_to_noise(uint32_t bits)
{
    const uint32_t mant = bits >> 9;
    const float fl = __uint_as_float(0x3F800000u | mant) - 1.0f;  // exact m*2^-23
    float L;
    const float d = 1.0f - fl;
    if (d <= 0.015625f) {
        L = d * (1.0f + d * (0.5f + d * (0.3333333432674408f + d * 0.25f)));
    } else if (mant == 0u) {
        L = 87.336544750553109f;                                  // -ln(2^-126)
    } else {
        L = -0.69314718055994531f * __log2f(fl);
    }
    return -2.0f * __log2f(L);
}

// One noise block = 2048 elements of iteration i = b>>6, chunk = b&63.
__global__ __launch_bounds__(256) void noise_all()
{
    const int b = (int)blockIdx.x;
    const int i = b >> 6;
    const uint2 key = g_keys[i];
    const uint32_t k1 = key.x, k2 = key.y;
    const uint32_t ks2 = k1 ^ k2 ^ 0x1BD11BDAu;
    const uint32_t jbase = (uint32_t)(b & 63) * 2048u + threadIdx.x;
    float* out = g_noise + (size_t)i * 131072u;
#pragma unroll
    for (int t = 0; t < 8; t++) {
        uint32_t j = jbase + (uint32_t)t * 256u;
        uint32_t o0, o1;
        tf_block(k1, k2, ks2, 0u, j, o0, o1);
        out[j] = bits_to_noise(o0 ^ o1);
    }
    __syncthreads();
    if (threadIdx.x == 0) {
        __threadfence();
        atomicAdd(&g_icnt[i], 1);
    }
}

// ---------------------------------------------------------------------------
// Scalar GEMM: 64 x N fp32, 64x64 tile/CTA, 256 threads, 4x4/thread,
// double-buffered smem, K-split -> raw partials.
// ---------------------------------------------------------------------------
template <int COLTILES, int KSPLIT>
__global__ __launch_bounds__(256) void gemm_k(const float* __restrict__ X,
                                              const float* __restrict__ W,
                                              float* __restrict__ P,
                                              int K, int N)
{
    __shared__ __align__(16) float Xs[2][1024];   // [kk][m]
    __shared__ __align__(16) float Ws[2][1024];   // [kk][n]

    const int tid = threadIdx.x;
    const int tx = tid & 15, ty = tid >> 4;
    const int col = blockIdx.x % COLTILES;
    const int kc  = blockIdx.x / COLTILES;
    const int cb  = col * 64;
    const int Kc  = K / KSPLIT;
    const int k0  = kc * Kc;

    const int lm = tid >> 2;
    const int lk = (tid & 3) << 2;
    const int wk = tid >> 4;
    const int wn = (tid & 15) << 2;

    float acc[4][4] = {};

    float4 xa = *reinterpret_cast<const float4*>(X + (size_t)lm * K + k0 + lk);
    float4 wa = *reinterpret_cast<const float4*>(W + (size_t)(k0 + wk) * N + cb + wn);
    Xs[0][(lk + 0) * 64 + lm] = xa.x;
    Xs[0][(lk + 1) * 64 + lm] = xa.y;
    Xs[0][(lk + 2) * 64 + lm] = xa.z;
    Xs[0][(lk + 3) * 64 + lm] = xa.w;
    *reinterpret_cast<float4*>(&Ws[0][wk * 64 + wn]) = wa;
    __syncthreads();

    const int nt = Kc >> 4;
    int buf = 0;
    for (int t = 0; t < nt; t++) {
        float4 xn, wn4;
        const bool more = (t + 1 < nt);
        if (more) {
            int kk0 = k0 + ((t + 1) << 4);
            xn  = *reinterpret_cast<const float4*>(X + (size_t)lm * K + kk0 + lk);
            wn4 = *reinterpret_cast<const float4*>(W + (size_t)(kk0 + wk) * N + cb + wn);
        }
#pragma unroll
        for (int kk = 0; kk < 16; kk++) {
            const float4 a4 = *reinterpret_cast<const float4*>(&Xs[buf][(kk << 6) + (ty << 2)]);
            const float4 b4 = *reinterpret_cast<const float4*>(&Ws[buf][(kk << 6) + (tx << 2)]);
            const float av[4] = {a4.x, a4.y, a4.z, a4.w};
            const float bv[4] = {b4.x, b4.y, b4.z, b4.w};
#pragma unroll
            for (int i2 = 0; i2 < 4; i2++)
#pragma unroll
                for (int j2 = 0; j2 < 4; j2++)
                    acc[i2][j2] = fmaf(av[i2], bv[j2], acc[i2][j2]);
        }
        if (more) {
            const int nb = buf ^ 1;
            Xs[nb][(lk + 0) * 64 + lm] = xn.x;
            Xs[nb][(lk + 1) * 64 + lm] = xn.y;
            Xs[nb][(lk + 2) * 64 + lm] = xn.z;
            Xs[nb][(lk + 3) * 64 + lm] = xn.w;
            *reinterpret_cast<float4*>(&Ws[nb][wk * 64 + wn]) = wn4;
            buf = nb;
        }
        __syncthreads();
    }

    float* dst = P + (size_t)kc * 64 * N;
#pragma unroll
    for (int i = 0; i < 4; i++) {
        float4 o = make_float4(acc[i][0], acc[i][1], acc[i][2], acc[i][3]);
        *reinterpret_cast<float4*>(dst + (size_t)((ty << 2) + i) * N + cb + (tx << 2)) = o;
    }
}

// ---------------------------------------------------------------------------
// K-split reduce + bias + batch-BN (+ affine + ReLU). One col/thread.
// ---------------------------------------------------------------------------
template <bool AR, int S>
__global__ __launch_bounds__(256) void reduce_k(const float* __restrict__ P,
                                                const float* __restrict__ bias,
                                                const float* __restrict__ gamma,
                                                const float* __restrict__ beta,
                                                float* __restrict__ Y, int N)
{
    const int c = blockIdx.x * 256 + threadIdx.x;
    const float b = bias[c];
    float s = 0.f, ss = 0.f;
#pragma unroll 4
    for (int r = 0; r < 64; r++) {
        float v = b;
#pragma unroll
        for (int q = 0; q < S; q++) v += P[((size_t)q * 64 + r) * N + c];
        s += v; ss += v * v;
    }
    const float mean = s * 0.015625f;
    const float inv  = rsqrtf(fmaf(-mean, mean, ss * 0.015625f) + 1e-5f);
    const float ga = AR ? gamma[c] : 1.0f;
    const float be = AR ? beta[c]  : 0.0f;
#pragma unroll 4
    for (int r = 0; r < 64; r++) {
        float v = b;
#pragma unroll
        for (int q = 0; q < S; q++) v += P[((size_t)q * 64 + r) * N + c];
        float y = (v - mean) * inv;
        if (AR) y = fmaxf(fmaf(y, ga, be), 0.0f);
        Y[(size_t)r * N + c] = y;
    }
}

// ---------------------------------------------------------------------------
// Iteration kernel: 64 CTAs (one row each), 256 thr, 8 cols/thread.
// Gated on g_icnt watermarks (noise runs concurrently on another stream).
// ---------------------------------------------------------------------------
__device__ __forceinline__ float ex2f(float x)
{
    float y; asm("ex2.approx.f32 %0, %1;" : "=f"(y) : "f"(x)); return y;
}

__global__ __launch_bounds__(256) void iter_k(float* __restrict__ zout)
{
    const int row  = blockIdx.x;
    const int tid  = threadIdx.x;
    const int lane = tid & 31, wid = tid >> 5;
    const float C = 2.8853900817779268f;   // 2*log2(e)

    float4 ma = *(const float4*)(g_mask0 + row * 2048 + 8 * tid);
    float4 mb = *(const float4*)(g_mask0 + row * 2048 + 8 * tid + 4);
    float4 za = make_float4(0.f, 0.f, 0.f, 0.f);
    float4 zb = make_float4(0.f, 0.f, 0.f, 0.f);

    __shared__ __align__(16) float wsum[2][8];
    volatile int* icnt = (volatile int*)g_icnt;

    const float4* np = (const float4*)g_noise + (size_t)row * 512 + 2 * tid;

    // initial gate: iterations 0..16 ready
    if (tid == 0) {
        for (int w = 0; w <= 16; w++)
            while (icnt[w] < 64) __nanosleep(128);
        __threadfence();
    }
    __syncthreads();
    float4 na = np[0], nb = np[1];

    for (int i = 0; i < 1024; i++) {
        const float4 ca = na, cb = nb;

        const float e0 = ex2f(fmaf(ma.x, C, ca.x));
        const float e1 = ex2f(fmaf(ma.y, C, ca.y));
        const float e2 = ex2f(fmaf(ma.z, C, ca.z));
        const float e3 = ex2f(fmaf(ma.w, C, ca.w));
        const float e4 = ex2f(fmaf(mb.x, C, cb.x));
        const float e5 = ex2f(fmaf(mb.y, C, cb.y));
        const float e6 = ex2f(fmaf(mb.z, C, cb.z));
        const float e7 = ex2f(fmaf(mb.w, C, cb.w));
        float s = ((e0 + e1) + (e2 + e3)) + ((e4 + e5) + (e6 + e7));
#pragma unroll
        for (int o = 16; o; o >>= 1) s += __shfl_xor_sync(0xffffffffu, s, o);
        if (lane == 0) wsum[i & 1][wid] = s;

        // watermark: iterations [i+1, i+16] ready (checked every 8 iters)
        if (tid == 0 && (i & 7) == 0) {
            const int hi = (i + 16 < 1023) ? i + 16 : 1023;
            for (int w = i + 1; w <= hi; w++)
                while (icnt[w] < 64) __nanosleep(128);
            __threadfence();
        }
        __syncthreads();

        const float4* wp = (const float4*)wsum[i & 1];
        const float4 t0 = wp[0], t1 = wp[1];
        const float tt = ((t0.x + t0.y) + (t0.z + t0.w)) + ((t1.x + t1.y) + (t1.z + t1.w));
        float r; asm("rcp.approx.f32 %0, %1;" : "=f"(r) : "f"(tt));
        ma.x = e0 * r; ma.y = e1 * r; ma.z = e2 * r; ma.w = e3 * r;
        mb.x = e4 * r; mb.y = e5 * r; mb.z = e6 * r; mb.w = e7 * r;
        za.x = fmaxf(za.x, ma.x); za.y = fmaxf(za.y, ma.y);
        za.z = fmaxf(za.z, ma.z); za.w = fmaxf(za.w, ma.w);
        zb.x = fmaxf(zb.x, mb.x); zb.y = fmaxf(zb.y, mb.y);
        zb.z = fmaxf(zb.z, mb.z); zb.w = fmaxf(zb.w, mb.w);

        if (i < 1023) {
            na = np[(size_t)(i + 1) * 32768];
            nb = np[(size_t)(i + 1) * 32768 + 1];
        }
    }
    *(float4*)(zout + row * 2048 + 8 * tid)     = za;
    *(float4*)(zout + row * 2048 + 8 * tid + 4) = zb;
}

// ---------------------------------------------------------------------------
// Launch: fork noise onto a low-priority stream, gemm chain + iter on the
// main stream, rejoin for graph completeness. All graph-capturable.
// ---------------------------------------------------------------------------
extern "C" void kernel_launch(void* const* d_in, const int* in_sizes, int n_in,
                              void* d_out, int out_size)
{
    const float* f   = (const float*)d_in[0];
    const float* W1  = (const float*)d_in[1];
    const float* b1  = (const float*)d_in[2];
    const float* g1  = (const float*)d_in[3];
    const float* be1 = (const float*)d_in[4];
    const float* W2  = (const float*)d_in[5];
    const float* b2  = (const float*)d_in[6];
    const float* g2  = (const float*)d_in[7];
    const float* be2 = (const float*)d_in[8];
    const float* W3  = (const float*)d_in[9];
    const float* b3  = (const float*)d_in[10];
    float* out = (float*)d_out;

    void *p1, *p2, *p3, *pp, *pp3;
    cudaGetSymbolAddress(&p1, g_h1);
    cudaGetSymbolAddress(&p2, g_h2);
    cudaGetSymbolAddress(&p3, g_mask0);
    cudaGetSymbolAddress(&pp, g_p);
    cudaGetSymbolAddress(&pp3, g_p3);
    float* h1 = (float*)p1;
    float* h2 = (float*)p2;
    float* mk = (float*)p3;
    float* P  = (float*)pp;
    float* P3 = (float*)pp3;

    // low-priority side stream for the noise kernel (host objects; created
    // on each of the few kernel_launch invocations, never during replay)
    int prLo = 0, prHi = 0;
    cudaDeviceGetStreamPriorityRange(&prLo, &prHi);
    cudaStream_t sN;
    cudaStreamCreateWithPriority(&sN, cudaStreamNonBlocking, prLo);
    cudaEvent_t evFork, evJoin;
    cudaEventCreateWithFlags(&evFork, cudaEventDisableTiming);
    cudaEventCreateWithFlags(&evJoin, cudaEventDisableTiming);

    // main stream: init
    keys_kernel<<<1, 1024>>>();

    // fork: noise depends on keys, runs concurrently at low priority
    cudaEventRecord(evFork, 0);
    cudaStreamWaitEvent(sN, evFork, 0);
    noise_all<<<65536, 256, 0, sN>>>();

    // main stream: gemm chain (pure, deep K-splits)
    gemm_k<128, 4><<<512, 256>>>(f,  W1, P, 2048, 8192);
    reduce_k<true, 4><<<32, 256>>>(P, b1, g1, be1, h1, 8192);

    gemm_k<128, 8><<<1024, 256>>>(h1, W2, P, 8192, 8192);
    reduce_k<true, 8><<<32, 256>>>(P, b2, g2, be2, h2, 8192);

    gemm_k<32, 8><<<256, 256>>>(h2, W3, P3, 8192, 2048);
    reduce_k<false, 8><<<8, 256>>>(P3, b3, nullptr, nullptr, mk, 2048);

    // iteration chains: gated on g_icnt, overlaps the noise tail
    iter_k<<<64, 256>>>(out);

    // join the side stream back so the captured graph is fully connected
    cudaEventRecord(evJoin, sN);
    cudaStreamWaitEvent(0, evJoin, 0);
}

// round 12
// speedup vs baseline: 1.2808x; 1.2808x over previous
#include <cuda_runtime.h>
#include <cstdint>
#include <cstddef>

typedef unsigned long long u64;

// ---------------------------------------------------------------------------
// Scratch (device globals — no allocation allowed)
// ---------------------------------------------------------------------------
__device__ float g_noise[(size_t)1024 * 131072];   // 512 MiB prescaled gumbel noise
__device__ float g_h1[64 * 8192];
__device__ float g_h2[64 * 8192];
__device__ float g_mask0[64 * 2048];
__device__ float g_p [(size_t)8 * 64 * 8192];      // K-split partials (g1 x4 / g2 x8)
__device__ float g_p3[(size_t)8 * 64 * 2048];      // gemm3 x8 partials
__device__ uint2 g_keys[1024];
__device__ int   g_icnt[1024];                     // per-iteration noise arrivals

// ---------------------------------------------------------------------------
// f32x2 packed FMA (Blackwell, base PTX)
// ---------------------------------------------------------------------------
#define FMA2(acc, a2, b2) asm("fma.rn.f32x2 %0, %1, %2, %0;" : "+l"(acc) : "l"(a2), "l"(b2))
#define PK2(d, lo, hi)    asm("mov.b64 %0, {%1, %2};" : "=l"(d) : "r"(lo), "r"(hi))
#define UPK2(lo, hi, s)   asm("mov.b64 {%0, %1}, %2;" : "=r"(lo), "=r"(hi) : "l"(s))

// ---------------------------------------------------------------------------
// Threefry-2x32-20 (bit-exact JAX)
// ---------------------------------------------------------------------------
__device__ __forceinline__ void tf_block(uint32_t ks0, uint32_t ks1, uint32_t ks2,
                                         uint32_t x0, uint32_t x1,
                                         uint32_t& o0, uint32_t& o1)
{
    x0 += ks0; x1 += ks1;
#define TFR(r) { x0 += x1; x1 = __funnelshift_l(x1, x1, (r)); x1 ^= x0; }
    TFR(13); TFR(15); TFR(26); TFR(6);
    x0 += ks1; x1 += ks2 + 1u;
    TFR(17); TFR(29); TFR(16); TFR(24);
    x0 += ks2; x1 += ks0 + 2u;
    TFR(13); TFR(15); TFR(26); TFR(6);
    x0 += ks0; x1 += ks1 + 3u;
    TFR(17); TFR(29); TFR(16); TFR(24);
    x0 += ks1; x1 += ks2 + 4u;
    TFR(13); TFR(15); TFR(26); TFR(6);
    x0 += ks2; x1 += ks0 + 5u;
#undef TFR
    o0 = x0; o1 = x1;
}

// per-replay init: reset counters + fold per-iteration keys
__global__ void keys_kernel()
{
    int i = threadIdx.x;
    g_icnt[i] = 0;
    uint32_t o0, o1;
    tf_block(0u, 42u, 0u ^ 42u ^ 0x1BD11BDAu, 0u, (uint32_t)i, o0, o1);
    g_keys[i] = make_uint2(o0, o1);
}

// bits -> n = -2*log2(-ln u)  so the iter loop is e = 2^(mask*C + n), C = 2*log2(e)
__device__ __forceinline__ float bits_to_noise(uint32_t bits)
{
    const uint32_t mant = bits >> 9;
    const float fl = __uint_as_float(0x3F800000u | mant) - 1.0f;  // exact m*2^-23
    float L;
    const float d = 1.0f - fl;
    if (d <= 0.015625f) {
        L = d * (1.0f + d * (0.5f + d * (0.3333333432674408f + d * 0.25f)));
    } else if (mant == 0u) {
        L = 87.336544750553109f;                                  // -ln(2^-126)
    } else {
        L = -0.69314718055994531f * __log2f(fl);
    }
    return -2.0f * __log2f(L);
}

// One noise block = 2048 elements of iteration i = b>>6, chunk = b&63.
template <int TPB>
__device__ __forceinline__ void noise_body(int b)
{
    const int i = b >> 6;
    const uint2 key = g_keys[i];
    const uint32_t k1 = key.x, k2 = key.y;
    const uint32_t ks2 = k1 ^ k2 ^ 0x1BD11BDAu;
    const uint32_t jbase = (uint32_t)(b & 63) * 2048u + threadIdx.x;
    float* out = g_noise + (size_t)i * 131072u;
#pragma unroll 8
    for (int t = 0; t < 2048 / TPB; t++) {
        uint32_t j = jbase + (uint32_t)t * TPB;
        uint32_t o0, o1;
        tf_block(k1, k2, ks2, 0u, j, o0, o1);
        out[j] = bits_to_noise(o0 ^ o1);
    }
    __syncthreads();
    if (threadIdx.x == 0) {
        __threadfence();
        atomicAdd(&g_icnt[i], 1);
    }
}

// ---------------------------------------------------------------------------
// FFMA2 GEMM: 64 x N fp32, 64x64 tile/CTA, 256 threads, 4x4/thread with
// paired-column u64 accumulators (halves fma-pipe instruction count),
// double-buffered smem, K-split -> raw partials. Extra CTAs generate noise.
// ---------------------------------------------------------------------------
template <int COLTILES, int KSPLIT>
__global__ __launch_bounds__(256) void gemm_noise(const float* __restrict__ X,
                                                  const float* __restrict__ W,
                                                  float* __restrict__ P,
                                                  int K, int N, int noiseBase)
{
    constexpr int GC = COLTILES * KSPLIT;
    if (blockIdx.x >= GC) { noise_body<256>(noiseBase + (int)blockIdx.x - GC); return; }

    __shared__ __align__(16) float Xs[2][1024];   // [kk][m]
    __shared__ __align__(16) float Ws[2][1024];   // [kk][n]

    const int tid = threadIdx.x;
    const int tx = tid & 15, ty = tid >> 4;
    const int col = blockIdx.x % COLTILES;
    const int kc  = blockIdx.x / COLTILES;
    const int cb  = col * 64;
    const int Kc  = K / KSPLIT;
    const int k0  = kc * Kc;

    const int lm = tid >> 2;
    const int lk = (tid & 3) << 2;
    const int wk = tid >> 4;
    const int wn = (tid & 15) << 2;

    u64 acc[4][2];
#pragma unroll
    for (int i = 0; i < 4; i++) { acc[i][0] = 0ull; acc[i][1] = 0ull; }

    float4 xa = *reinterpret_cast<const float4*>(X + (size_t)lm * K + k0 + lk);
    float4 wa = *reinterpret_cast<const float4*>(W + (size_t)(k0 + wk) * N + cb + wn);
    Xs[0][(lk + 0) * 64 + lm] = xa.x;
    Xs[0][(lk + 1) * 64 + lm] = xa.y;
    Xs[0][(lk + 2) * 64 + lm] = xa.z;
    Xs[0][(lk + 3) * 64 + lm] = xa.w;
    *reinterpret_cast<float4*>(&Ws[0][wk * 64 + wn]) = wa;
    __syncthreads();

    const int nt = Kc >> 4;
    int buf = 0;
    for (int t = 0; t < nt; t++) {
        float4 xn, wn4;
        const bool more = (t + 1 < nt);
        if (more) {
            int kk0 = k0 + ((t + 1) << 4);
            xn  = *reinterpret_cast<const float4*>(X + (size_t)lm * K + kk0 + lk);
            wn4 = *reinterpret_cast<const float4*>(W + (size_t)(kk0 + wk) * N + cb + wn);
        }
#pragma unroll
        for (int kk = 0; kk < 16; kk++) {
            const float4 a4 = *reinterpret_cast<const float4*>(&Xs[buf][(kk << 6) + (ty << 2)]);
            const float4 b4 = *reinterpret_cast<const float4*>(&Ws[buf][(kk << 6) + (tx << 2)]);
            u64 bp0, bp1, ad0, ad1, ad2, ad3;
            PK2(bp0, __float_as_uint(b4.x), __float_as_uint(b4.y));
            PK2(bp1, __float_as_uint(b4.z), __float_as_uint(b4.w));
            PK2(ad0, __float_as_uint(a4.x), __float_as_uint(a4.x));
            PK2(ad1, __float_as_uint(a4.y), __float_as_uint(a4.y));
            PK2(ad2, __float_as_uint(a4.z), __float_as_uint(a4.z));
            PK2(ad3, __float_as_uint(a4.w), __float_as_uint(a4.w));
            FMA2(acc[0][0], ad0, bp0); FMA2(acc[0][1], ad0, bp1);
            FMA2(acc[1][0], ad1, bp0); FMA2(acc[1][1], ad1, bp1);
            FMA2(acc[2][0], ad2, bp0); FMA2(acc[2][1], ad2, bp1);
            FMA2(acc[3][0], ad3, bp0); FMA2(acc[3][1], ad3, bp1);
        }
        if (more) {
            const int nb = buf ^ 1;
            Xs[nb][(lk + 0) * 64 + lm] = xn.x;
            Xs[nb][(lk + 1) * 64 + lm] = xn.y;
            Xs[nb][(lk + 2) * 64 + lm] = xn.z;
            Xs[nb][(lk + 3) * 64 + lm] = xn.w;
            *reinterpret_cast<float4*>(&Ws[nb][wk * 64 + wn]) = wn4;
            buf = nb;
        }
        __syncthreads();
    }

    // raw partials: P[kc][m][n]
    float* dst = P + (size_t)kc * 64 * N;
#pragma unroll
    for (int i = 0; i < 4; i++) {
        uint32_t f0, f1, f2, f3;
        UPK2(f0, f1, acc[i][0]);
        UPK2(f2, f3, acc[i][1]);
        float4 o = make_float4(__uint_as_float(f0), __uint_as_float(f1),
                               __uint_as_float(f2), __uint_as_float(f3));
        *reinterpret_cast<float4*>(dst + (size_t)((ty << 2) + i) * N + cb + (tx << 2)) = o;
    }
}

// ---------------------------------------------------------------------------
// K-split reduce + bias + batch-BN (+ affine + ReLU). Extra CTAs = noise.
// ---------------------------------------------------------------------------
template <bool AR, int S, int RED>
__global__ __launch_bounds__(256) void reduce_noise(const float* __restrict__ P,
                                                    const float* __restrict__ bias,
                                                    const float* __restrict__ gamma,
                                                    const float* __restrict__ beta,
                                                    float* __restrict__ Y, int N,
                                                    int noiseBase)
{
    if (blockIdx.x >= RED) { noise_body<256>(noiseBase + (int)blockIdx.x - RED); return; }

    const int c = blockIdx.x * 256 + threadIdx.x;
    const float b = bias[c];
    float s = 0.f, ss = 0.f;
#pragma unroll 4
    for (int r = 0; r < 64; r++) {
        float v = b;
#pragma unroll
        for (int q = 0; q < S; q++) v += P[((size_t)q * 64 + r) * N + c];
        s += v; ss += v * v;
    }
    const float mean = s * 0.015625f;
    const float inv  = rsqrtf(fmaf(-mean, mean, ss * 0.015625f) + 1e-5f);
    const float ga = AR ? gamma[c] : 1.0f;
    const float be = AR ? beta[c]  : 0.0f;
#pragma unroll 4
    for (int r = 0; r < 64; r++) {
        float v = b;
#pragma unroll
        for (int q = 0; q < S; q++) v += P[((size_t)q * 64 + r) * N + c];
        float y = (v - mean) * inv;
        if (AR) y = fmaxf(fmaf(y, ga, be), 0.0f);
        Y[(size_t)r * N + c] = y;
    }
}

// ---------------------------------------------------------------------------
// Iteration kernel: blockIdx 0..63 = row chains (256 thr, 8 cols/thread);
// small noise tail (iterations 928..1023) on the remaining CTAs.
// ---------------------------------------------------------------------------
__device__ __forceinline__ float ex2f(float x)
{
    float y; asm("ex2.approx.f32 %0, %1;" : "=f"(y) : "f"(x)); return y;
}

__global__ __launch_bounds__(256) void iter_noise(float* __restrict__ zout,
                                                  int noiseBase, int gateFrom)
{
    if (blockIdx.x >= 64) { noise_body<256>(noiseBase + (int)blockIdx.x - 64); return; }

    const int row  = blockIdx.x;
    const int tid  = threadIdx.x;
    const int lane = tid & 31, wid = tid >> 5;
    const float C = 2.8853900817779268f;   // 2*log2(e)

    float4 ma = *(const float4*)(g_mask0 + row * 2048 + 8 * tid);
    float4 mb = *(const float4*)(g_mask0 + row * 2048 + 8 * tid + 4);
    float4 za = make_float4(0.f, 0.f, 0.f, 0.f);
    float4 zb = make_float4(0.f, 0.f, 0.f, 0.f);

    __shared__ __align__(16) float wsum[2][8];
    volatile int* icnt = (volatile int*)g_icnt;

    const float4* np = (const float4*)g_noise + (size_t)row * 512 + 2 * tid;
    float4 na = np[0], nb = np[1];   // iterations < 928 complete before launch

    for (int i = 0; i < 1024; i++) {
        const float4 ca = na, cb = nb;

        const float e0 = ex2f(fmaf(ma.x, C, ca.x));
        const float e1 = ex2f(fmaf(ma.y, C, ca.y));
        const float e2 = ex2f(fmaf(ma.z, C, ca.z));
        const float e3 = ex2f(fmaf(ma.w, C, ca.w));
        const float e4 = ex2f(fmaf(mb.x, C, cb.x));
        const float e5 = ex2f(fmaf(mb.y, C, cb.y));
        const float e6 = ex2f(fmaf(mb.z, C, cb.z));
        const float e7 = ex2f(fmaf(mb.w, C, cb.w));
        float s = ((e0 + e1) + (e2 + e3)) + ((e4 + e5) + (e6 + e7));
#pragma unroll
        for (int o = 16; o; o >>= 1) s += __shfl_xor_sync(0xffffffffu, s, o);
        if (lane == 0) wsum[i & 1][wid] = s;

        // readiness watermark for the in-flight tail (covers prefetch window)
        if (tid == 0 && (i & 7) == 0 && i >= gateFrom) {
            const int hi = (i + 16 < 1023) ? i + 16 : 1023;
            for (int w = i + 1; w <= hi; w++)
                while (icnt[w] < 64) __nanosleep(128);
            __threadfence();
        }
        __syncthreads();

        const float4* wp = (const float4*)wsum[i & 1];
        const float4 t0 = wp[0], t1 = wp[1];
        const float tt = ((t0.x + t0.y) + (t0.z + t0.w)) + ((t1.x + t1.y) + (t1.z + t1.w));
        float r; asm("rcp.approx.f32 %0, %1;" : "=f"(r) : "f"(tt));
        ma.x = e0 * r; ma.y = e1 * r; ma.z = e2 * r; ma.w = e3 * r;
        mb.x = e4 * r; mb.y = e5 * r; mb.z = e6 * r; mb.w = e7 * r;
        za.x = fmaxf(za.x, ma.x); za.y = fmaxf(za.y, ma.y);
        za.z = fmaxf(za.z, ma.z); za.w = fmaxf(za.w, ma.w);
        zb.x = fmaxf(zb.x, mb.x); zb.y = fmaxf(zb.y, mb.y);
        zb.z = fmaxf(zb.z, mb.z); zb.w = fmaxf(zb.w, mb.w);

        if (i < 1023) {
            na = np[(size_t)(i + 1) * 32768];
            nb = np[(size_t)(i + 1) * 32768 + 1];
        }
    }
    *(float4*)(zout + row * 2048 + 8 * tid)     = za;
    *(float4*)(zout + row * 2048 + 8 * tid + 4) = zb;
}

// ---------------------------------------------------------------------------
// Launch
// ---------------------------------------------------------------------------
extern "C" void kernel_launch(void* const* d_in, const int* in_sizes, int n_in,
                              void* d_out, int out_size)
{
    const float* f   = (const float*)d_in[0];
    const float* W1  = (const float*)d_in[1];
    const float* b1  = (const float*)d_in[2];
    const float* g1  = (const float*)d_in[3];
    const float* be1 = (const float*)d_in[4];
    const float* W2  = (const float*)d_in[5];
    const float* b2  = (const float*)d_in[6];
    const float* g2  = (const float*)d_in[7];
    const float* be2 = (const float*)d_in[8];
    const float* W3  = (const float*)d_in[9];
    const float* b3  = (const float*)d_in[10];
    float* out = (float*)d_out;

    void *p1, *p2, *p3, *pp, *pp3;
    cudaGetSymbolAddress(&p1, g_h1);
    cudaGetSymbolAddress(&p2, g_h2);
    cudaGetSymbolAddress(&p3, g_mask0);
    cudaGetSymbolAddress(&pp, g_p);
    cudaGetSymbolAddress(&pp3, g_p3);
    float* h1 = (float*)p1;
    float* h2 = (float*)p2;
    float* mk = (float*)p3;
    float* P  = (float*)pp;
    float* P3 = (float*)pp3;

    // noise block bases (65536 total, iteration-ordered):
    //  g1 13312 @0      r1 3072 @13312   g2 24576 @16384
    //  r2 3072 @40960   g3 12288 @44032  r3 3072 @56320
    //  iter tail 6144 @59392 (iterations 928..1023)
    keys_kernel<<<1, 1024>>>();

    gemm_noise<128, 4><<<512 + 13312, 256>>>(f,  W1, P, 2048, 8192, 0);
    reduce_noise<true, 4, 32><<<32 + 3072, 256>>>(P, b1, g1, be1, h1, 8192, 13312);

    gemm_noise<128, 8><<<1024 + 24576, 256>>>(h1, W2, P, 8192, 8192, 16384);
    reduce_noise<true, 8, 32><<<32 + 3072, 256>>>(P, b2, g2, be2, h2, 8192, 40960);

    gemm_noise<32, 8><<<256 + 12288, 256>>>(h2, W3, P3, 8192, 2048, 44032);
    reduce_noise<false, 8, 8><<<8 + 3072, 256>>>(P3, b3, nullptr, nullptr, mk, 2048, 56320);

    iter_noise<<<64 + 6144, 256>>>(out, 59392, 896);
}

// round 13
// speedup vs baseline: 1.4036x; 1.0959x over previous
#include <cuda_runtime.h>
#include <cstdint>
#include <cstddef>

// ---------------------------------------------------------------------------
// Scratch (device globals — no allocation allowed)
// ---------------------------------------------------------------------------
__device__ float g_noise[(size_t)1024 * 131072];   // 512 MiB prescaled gumbel noise
__device__ float g_h1[64 * 8192];
__device__ float g_h2[64 * 8192];
__device__ float g_mask0[64 * 2048];
__device__ float g_p [(size_t)8 * 64 * 8192];      // K-split partials (g1 x4 / g2 x8)
__device__ float g_p3[(size_t)8 * 64 * 2048];      // gemm3 x8 partials
__device__ uint2 g_keys[1024];

// ---------------------------------------------------------------------------
// Threefry-2x32-20 (bit-exact JAX)
// ---------------------------------------------------------------------------
__device__ __forceinline__ void tf_block(uint32_t ks0, uint32_t ks1, uint32_t ks2,
                                         uint32_t x0, uint32_t x1,
                                         uint32_t& o0, uint32_t& o1)
{
    x0 += ks0; x1 += ks1;
#define TFR(r) { x0 += x1; x1 = __funnelshift_l(x1, x1, (r)); x1 ^= x0; }
    TFR(13); TFR(15); TFR(26); TFR(6);
    x0 += ks1; x1 += ks2 + 1u;
    TFR(17); TFR(29); TFR(16); TFR(24);
    x0 += ks2; x1 += ks0 + 2u;
    TFR(13); TFR(15); TFR(26); TFR(6);
    x0 += ks0; x1 += ks1 + 3u;
    TFR(17); TFR(29); TFR(16); TFR(24);
    x0 += ks1; x1 += ks2 + 4u;
    TFR(13); TFR(15); TFR(26); TFR(6);
    x0 += ks2; x1 += ks0 + 5u;
#undef TFR
    o0 = x0; o1 = x1;
}

// per-replay init: fold per-iteration keys
__global__ void keys_kernel()
{
    int i = threadIdx.x;
    uint32_t o0, o1;
    tf_block(0u, 42u, 0u ^ 42u ^ 0x1BD11BDAu, 0u, (uint32_t)i, o0, o1);
    g_keys[i] = make_uint2(o0, o1);
}

// bits -> n = -2*log2(-ln u)  so the iter loop is e = 2^(mask*C + n), C = 2*log2(e)
__device__ __forceinline__ float bits_to_noise(uint32_t bits)
{
    const uint32_t mant = bits >> 9;
    const float fl = __uint_as_float(0x3F800000u | mant) - 1.0f;  // exact m*2^-23
    float L;
    const float d = 1.0f - fl;
    if (d <= 0.015625f) {
        L = d * (1.0f + d * (0.5f + d * (0.3333333432674408f + d * 0.25f)));
    } else if (mant == 0u) {
        L = 87.336544750553109f;                                  // -ln(2^-126)
    } else {
        L = -0.69314718055994531f * __log2f(fl);
    }
    return -2.0f * __log2f(L);
}

// ---------------------------------------------------------------------------
// Noise warp-job: one warp generates 512 elements (16/thread).
// Global job g: iteration i = g>>8, chunk c = g&255 -> j in [c*512, c*512+512).
// 262144 jobs total = 1024 iterations x 256 chunks. No block syncs.
// ---------------------------------------------------------------------------
__device__ __forceinline__ void noise_jobs(int jobBase, int njobs)
{
    const int lane = threadIdx.x & 31;
    for (int q = 0; q < njobs; q++) {
        const int g = jobBase + q;
        const int i = g >> 8;
        const int c = g & 255;
        const uint2 key = g_keys[i];
        const uint32_t k1 = key.x, k2 = key.y;
        const uint32_t ks2 = k1 ^ k2 ^ 0x1BD11BDAu;
        float* out = g_noise + (size_t)i * 131072u + (uint32_t)c * 512u + lane;
        const uint32_t j0 = (uint32_t)c * 512u + lane;
#pragma unroll 8
        for (int t = 0; t < 16; t++) {
            uint32_t o0, o1;
            tf_block(k1, k2, ks2, 0u, j0 + (uint32_t)t * 32u, o0, o1);
            out[t * 32] = bits_to_noise(o0 ^ o1);
        }
    }
}

// ---------------------------------------------------------------------------
// Hybrid CTA: 512 threads. Warps 0-7 = noise (low wid -> low arbiter prio);
// warps 8-15 = gemm (high wid -> issue priority). Gemm uses named barrier 1
// so noise warps never participate in syncs.
// Gemm: 64 x N fp32, 64x64 tile, 8 warps, 4x4/thread scalar FFMA (pure fma
// pipe), double-buffered smem, K-split -> raw partials P[kc][64][N].
// ---------------------------------------------------------------------------
#define GBAR() asm volatile("bar.sync 1, 256;" ::: "memory")

template <int COLTILES, int KSPLIT, int JPW>
__global__ __launch_bounds__(512) void gemm_noise(const float* __restrict__ X,
                                                  const float* __restrict__ W,
                                                  float* __restrict__ P,
                                                  int K, int N, int jobBase)
{
    __shared__ __align__(16) float Xs[2][1024];   // [kk][m]
    __shared__ __align__(16) float Ws[2][1024];   // [kk][n]

    const int tid = threadIdx.x;
    const int wid = tid >> 5;

    if (wid < 8) {   // ---- noise role ----
        noise_jobs(jobBase + ((int)blockIdx.x * 8 + wid) * JPW, JPW);
        return;
    }

    // ---- gemm role (256 threads, tid2 in [0,256)) ----
    const int t2 = tid - 256;
    const int tx = t2 & 15, ty = t2 >> 4;
    const int col = blockIdx.x % COLTILES;
    const int kc  = blockIdx.x / COLTILES;
    const int cb  = col * 64;
    const int Kc  = K / KSPLIT;
    const int k0  = kc * Kc;

    const int lm = t2 >> 2;
    const int lk = (t2 & 3) << 2;
    const int wk = t2 >> 4;
    const int wn = (t2 & 15) << 2;

    float acc[4][4] = {};

    float4 xa = *reinterpret_cast<const float4*>(X + (size_t)lm * K + k0 + lk);
    float4 wa = *reinterpret_cast<const float4*>(W + (size_t)(k0 + wk) * N + cb + wn);
    Xs[0][(lk + 0) * 64 + lm] = xa.x;
    Xs[0][(lk + 1) * 64 + lm] = xa.y;
    Xs[0][(lk + 2) * 64 + lm] = xa.z;
    Xs[0][(lk + 3) * 64 + lm] = xa.w;
    *reinterpret_cast<float4*>(&Ws[0][wk * 64 + wn]) = wa;
    GBAR();

    const int nt = Kc >> 4;
    int buf = 0;
    for (int t = 0; t < nt; t++) {
        float4 xn, wn4;
        const bool more = (t + 1 < nt);
        if (more) {
            int kk0 = k0 + ((t + 1) << 4);
            xn  = *reinterpret_cast<const float4*>(X + (size_t)lm * K + kk0 + lk);
            wn4 = *reinterpret_cast<const float4*>(W + (size_t)(kk0 + wk) * N + cb + wn);
        }
#pragma unroll
        for (int kk = 0; kk < 16; kk++) {
            const float4 a4 = *reinterpret_cast<const float4*>(&Xs[buf][(kk << 6) + (ty << 2)]);
            const float4 b4 = *reinterpret_cast<const float4*>(&Ws[buf][(kk << 6) + (tx << 2)]);
            const float av[4] = {a4.x, a4.y, a4.z, a4.w};
            const float bv[4] = {b4.x, b4.y, b4.z, b4.w};
#pragma unroll
            for (int i2 = 0; i2 < 4; i2++)
#pragma unroll
                for (int j2 = 0; j2 < 4; j2++)
                    acc[i2][j2] = fmaf(av[i2], bv[j2], acc[i2][j2]);
        }
        if (more) {
            const int nb = buf ^ 1;
            Xs[nb][(lk + 0) * 64 + lm] = xn.x;
            Xs[nb][(lk + 1) * 64 + lm] = xn.y;
            Xs[nb][(lk + 2) * 64 + lm] = xn.z;
            Xs[nb][(lk + 3) * 64 + lm] = xn.w;
            *reinterpret_cast<float4*>(&Ws[nb][wk * 64 + wn]) = wn4;
            buf = nb;
        }
        GBAR();
    }

    float* dst = P + (size_t)kc * 64 * N;
#pragma unroll
    for (int i = 0; i < 4; i++) {
        float4 o = make_float4(acc[i][0], acc[i][1], acc[i][2], acc[i][3]);
        *reinterpret_cast<float4*>(dst + (size_t)((ty << 2) + i) * N + cb + (tx << 2)) = o;
    }
}

// ---------------------------------------------------------------------------
// K-split reduce + bias + batch-BN (+ affine + ReLU). Extra CTAs = pure noise
// (256 thr, 8 warps x JPW jobs each).
// ---------------------------------------------------------------------------
template <bool AR, int S, int RED, int JPW>
__global__ __launch_bounds__(256) void reduce_noise(const float* __restrict__ P,
                                                    const float* __restrict__ bias,
                                                    const float* __restrict__ gamma,
                                                    const float* __restrict__ beta,
                                                    float* __restrict__ Y, int N,
                                                    int jobBase)
{
    if (blockIdx.x >= RED) {
        const int b = (int)blockIdx.x - RED;
        const int wid = threadIdx.x >> 5;
        noise_jobs(jobBase + (b * 8 + wid) * JPW, JPW);
        return;
    }

    const int c = blockIdx.x * 256 + threadIdx.x;
    const float b = bias[c];
    float s = 0.f, ss = 0.f;
#pragma unroll 4
    for (int r = 0; r < 64; r++) {
        float v = b;
#pragma unroll
        for (int q = 0; q < S; q++) v += P[((size_t)q * 64 + r) * N + c];
        s += v; ss += v * v;
    }
    const float mean = s * 0.015625f;
    const float inv  = rsqrtf(fmaf(-mean, mean, ss * 0.015625f) + 1e-5f);
    const float ga = AR ? gamma[c] : 1.0f;
    const float be = AR ? beta[c]  : 0.0f;
#pragma unroll 4
    for (int r = 0; r < 64; r++) {
        float v = b;
#pragma unroll
        for (int q = 0; q < S; q++) v += P[((size_t)q * 64 + r) * N + c];
        float y = (v - mean) * inv;
        if (AR) y = fmaxf(fmaf(y, ga, be), 0.0f);
        Y[(size_t)r * N + c] = y;
    }
}

// ---------------------------------------------------------------------------
// Iteration kernel: pure (all noise complete before this launch).
// 64 CTAs (one row each), 256 thr, 8 cols/thread.
// ---------------------------------------------------------------------------
__device__ __forceinline__ float ex2f(float x)
{
    float y; asm("ex2.approx.f32 %0, %1;" : "=f"(y) : "f"(x)); return y;
}

__global__ __launch_bounds__(256) void iter_k(float* __restrict__ zout)
{
    const int row  = blockIdx.x;
    const int tid  = threadIdx.x;
    const int lane = tid & 31, wid = tid >> 5;
    const float C = 2.8853900817779268f;   // 2*log2(e)

    float4 ma = *(const float4*)(g_mask0 + row * 2048 + 8 * tid);
    float4 mb = *(const float4*)(g_mask0 + row * 2048 + 8 * tid + 4);
    float4 za = make_float4(0.f, 0.f, 0.f, 0.f);
    float4 zb = make_float4(0.f, 0.f, 0.f, 0.f);

    __shared__ __align__(16) float wsum[2][8];

    const float4* np = (const float4*)g_noise + (size_t)row * 512 + 2 * tid;
    float4 na = np[0], nb = np[1];

    for (int i = 0; i < 1024; i++) {
        const float4 ca = na, cb = nb;

        const float e0 = ex2f(fmaf(ma.x, C, ca.x));
        const float e1 = ex2f(fmaf(ma.y, C, ca.y));
        const float e2 = ex2f(fmaf(ma.z, C, ca.z));
        const float e3 = ex2f(fmaf(ma.w, C, ca.w));
        const float e4 = ex2f(fmaf(mb.x, C, cb.x));
        const float e5 = ex2f(fmaf(mb.y, C, cb.y));
        const float e6 = ex2f(fmaf(mb.z, C, cb.z));
        const float e7 = ex2f(fmaf(mb.w, C, cb.w));
        float s = ((e0 + e1) + (e2 + e3)) + ((e4 + e5) + (e6 + e7));
#pragma unroll
        for (int o = 16; o; o >>= 1) s += __shfl_xor_sync(0xffffffffu, s, o);
        if (lane == 0) wsum[i & 1][wid] = s;
        __syncthreads();

        const float4* wp = (const float4*)wsum[i & 1];
        const float4 t0 = wp[0], t1 = wp[1];
        const float tt = ((t0.x + t0.y) + (t0.z + t0.w)) + ((t1.x + t1.y) + (t1.z + t1.w));
        float r; asm("rcp.approx.f32 %0, %1;" : "=f"(r) : "f"(tt));
        ma.x = e0 * r; ma.y = e1 * r; ma.z = e2 * r; ma.w = e3 * r;
        mb.x = e4 * r; mb.y = e5 * r; mb.z = e6 * r; mb.w = e7 * r;
        za.x = fmaxf(za.x, ma.x); za.y = fmaxf(za.y, ma.y);
        za.z = fmaxf(za.z, ma.z); za.w = fmaxf(za.w, ma.w);
        zb.x = fmaxf(zb.x, mb.x); zb.y = fmaxf(zb.y, mb.y);
        zb.z = fmaxf(zb.z, mb.z); zb.w = fmaxf(zb.w, mb.w);

        if (i < 1023) {
            na = np[(size_t)(i + 1) * 32768];
            nb = np[(size_t)(i + 1) * 32768 + 1];
        }
    }
    *(float4*)(zout + row * 2048 + 8 * tid)     = za;
    *(float4*)(zout + row * 2048 + 8 * tid + 4) = zb;
}

// ---------------------------------------------------------------------------
// Launch. Job budget (512-elem warp-jobs), 262144 total, iteration-ordered:
//   g1: 512 CTAs x 8 warps x  8 =  32768  @0        (iters   0..127)
//   r1: 1024 noise CTAs x 8 x 4 =  32768  @32768    (iters 128..255)
//   g2: 1024 CTAs x 8 x 16     = 131072  @65536    (iters 256..767)
//   r2: 512 x 8 x 4            =  16384  @196608   (iters 768..831)
//   g3: 256 x 8 x 16           =  32768  @212992   (iters 832..959)
//   r3: 512 x 8 x 4            =  16384  @245760   (iters 960..1023)
// ---------------------------------------------------------------------------
extern "C" void kernel_launch(void* const* d_in, const int* in_sizes, int n_in,
                              void* d_out, int out_size)
{
    const float* f   = (const float*)d_in[0];
    const float* W1  = (const float*)d_in[1];
    const float* b1  = (const float*)d_in[2];
    const float* g1  = (const float*)d_in[3];
    const float* be1 = (const float*)d_in[4];
    const float* W2  = (const float*)d_in[5];
    const float* b2  = (const float*)d_in[6];
    const float* g2  = (const float*)d_in[7];
    const float* be2 = (const float*)d_in[8];
    const float* W3  = (const float*)d_in[9];
    const float* b3  = (const float*)d_in[10];
    float* out = (float*)d_out;

    void *p1, *p2, *p3, *pp, *pp3;
    cudaGetSymbolAddress(&p1, g_h1);
    cudaGetSymbolAddress(&p2, g_h2);
    cudaGetSymbolAddress(&p3, g_mask0);
    cudaGetSymbolAddress(&pp, g_p);
    cudaGetSymbolAddress(&pp3, g_p3);
    float* h1 = (float*)p1;
    float* h2 = (float*)p2;
    float* mk = (float*)p3;
    float* P  = (float*)pp;
    float* P3 = (float*)pp3;

    keys_kernel<<<1, 1024>>>();

    gemm_noise<128, 4, 8><<<512, 512>>>(f,  W1, P, 2048, 8192, 0);
    reduce_noise<true, 4, 32, 4><<<32 + 1024, 256>>>(P, b1, g1, be1, h1, 8192, 32768);

    gemm_noise<128, 8, 16><<<1024, 512>>>(h1, W2, P, 8192, 8192, 65536);
    reduce_noise<true, 8, 32, 4><<<32 + 512, 256>>>(P, b2, g2, be2, h2, 8192, 196608);

    gemm_noise<32, 8, 16><<<256, 512>>>(h2, W3, P3, 8192, 2048, 212992);
    reduce_noise<false, 8, 8, 4><<<8 + 512, 256>>>(P3, b3, nullptr, nullptr, mk, 2048, 245760);

    iter_k<<<64, 256>>>(out);
}

// round 14
// speedup vs baseline: 1.5734x; 1.1210x over previous
#include <cuda_runtime.h>
#include <cstdint>
#include <cstddef>

// ---------------------------------------------------------------------------
// Scratch (device globals — no allocation allowed)
// ---------------------------------------------------------------------------
__device__ float g_noise[(size_t)1024 * 131072];   // 512 MiB prescaled gumbel noise
__device__ float g_h1[64 * 8192];
__device__ float g_h2[64 * 8192];
__device__ float g_mask0[64 * 2048];
__device__ float g_p [(size_t)8 * 64 * 8192];      // K-split partials (g1 x4 / g2 x8)
__device__ float g_p3[(size_t)8 * 64 * 2048];      // gemm3 x8 partials
__device__ uint2 g_keys[1024];

// ---------------------------------------------------------------------------
// Threefry-2x32-20 (bit-exact JAX)
// ---------------------------------------------------------------------------
__device__ __forceinline__ void tf_block(uint32_t ks0, uint32_t ks1, uint32_t ks2,
                                         uint32_t x0, uint32_t x1,
                                         uint32_t& o0, uint32_t& o1)
{
    x0 += ks0; x1 += ks1;
#define TFR(r) { x0 += x1; x1 = __funnelshift_l(x1, x1, (r)); x1 ^= x0; }
    TFR(13); TFR(15); TFR(26); TFR(6);
    x0 += ks1; x1 += ks2 + 1u;
    TFR(17); TFR(29); TFR(16); TFR(24);
    x0 += ks2; x1 += ks0 + 2u;
    TFR(13); TFR(15); TFR(26); TFR(6);
    x0 += ks0; x1 += ks1 + 3u;
    TFR(17); TFR(29); TFR(16); TFR(24);
    x0 += ks1; x1 += ks2 + 4u;
    TFR(13); TFR(15); TFR(26); TFR(6);
    x0 += ks2; x1 += ks0 + 5u;
#undef TFR
    o0 = x0; o1 = x1;
}

// per-replay init: fold per-iteration keys
__global__ void keys_kernel()
{
    int i = threadIdx.x;
    uint32_t o0, o1;
    tf_block(0u, 42u, 0u ^ 42u ^ 0x1BD11BDAu, 0u, (uint32_t)i, o0, o1);
    g_keys[i] = make_uint2(o0, o1);
}

// bits -> n = -2*log2(-ln u)  so the iter loop is e = 2^(mask*C + n), C = 2*log2(e)
__device__ __forceinline__ float bits_to_noise(uint32_t bits)
{
    const uint32_t mant = bits >> 9;
    const float fl = __uint_as_float(0x3F800000u | mant) - 1.0f;  // exact m*2^-23
    float L;
    const float d = 1.0f - fl;
    if (d <= 0.015625f) {
        L = d * (1.0f + d * (0.5f + d * (0.3333333432674408f + d * 0.25f)));
    } else if (mant == 0u) {
        L = 87.336544750553109f;                                  // -ln(2^-126)
    } else {
        L = -0.69314718055994531f * __log2f(fl);
    }
    return -2.0f * __log2f(L);
}

// ---------------------------------------------------------------------------
// Noise warp-job: one warp generates 512 elements (16/thread).
// Global job g: iteration i = g>>8, chunk c = g&255 -> j in [c*512, c*512+512).
// 262144 jobs total = 1024 iterations x 256 chunks. No block syncs.
// ---------------------------------------------------------------------------
__device__ __forceinline__ void noise_jobs(int jobBase, int njobs)
{
    const int lane = threadIdx.x & 31;
    for (int q = 0; q < njobs; q++) {
        const int g = jobBase + q;
        const int i = g >> 8;
        const int c = g & 255;
        const uint2 key = g_keys[i];
        const uint32_t k1 = key.x, k2 = key.y;
        const uint32_t ks2 = k1 ^ k2 ^ 0x1BD11BDAu;
        float* out = g_noise + (size_t)i * 131072u + (uint32_t)c * 512u + lane;
        const uint32_t j0 = (uint32_t)c * 512u + lane;
#pragma unroll 8
        for (int t = 0; t < 16; t++) {
            uint32_t o0, o1;
            tf_block(k1, k2, ks2, 0u, j0 + (uint32_t)t * 32u, o0, o1);
            out[t * 32] = bits_to_noise(o0 ^ o1);
        }
    }
}

// ---------------------------------------------------------------------------
// Hybrid CTA: 512 threads. Warps 0-7 = noise (low wid -> low arbiter prio);
// warps 8-15 = gemm (high wid -> issue priority). Gemm uses named barrier 1
// so noise warps never participate in syncs.
// Gemm: 64 x N fp32, 64x64 tile, 8 warps, 4x4/thread scalar FFMA (pure fma
// pipe), double-buffered smem, K-split -> raw partials P[kc][64][N].
// ---------------------------------------------------------------------------
#define GBAR() asm volatile("bar.sync 1, 256;" ::: "memory")

template <int COLTILES, int KSPLIT, int JPW>
__global__ __launch_bounds__(512) void gemm_noise(const float* __restrict__ X,
                                                  const float* __restrict__ W,
                                                  float* __restrict__ P,
                                                  int K, int N, int jobBase)
{
    __shared__ __align__(16) float Xs[2][1024];   // [kk][m]
    __shared__ __align__(16) float Ws[2][1024];   // [kk][n]

    const int tid = threadIdx.x;
    const int wid = tid >> 5;

    if (wid < 8) {   // ---- noise role ----
        noise_jobs(jobBase + ((int)blockIdx.x * 8 + wid) * JPW, JPW);
        return;
    }

    // ---- gemm role (256 threads, tid2 in [0,256)) ----
    const int t2 = tid - 256;
    const int tx = t2 & 15, ty = t2 >> 4;
    const int col = blockIdx.x % COLTILES;
    const int kc  = blockIdx.x / COLTILES;
    const int cb  = col * 64;
    const int Kc  = K / KSPLIT;
    const int k0  = kc * Kc;

    const int lm = t2 >> 2;
    const int lk = (t2 & 3) << 2;
    const int wk = t2 >> 4;
    const int wn = (t2 & 15) << 2;

    float acc[4][4] = {};

    float4 xa = *reinterpret_cast<const float4*>(X + (size_t)lm * K + k0 + lk);
    float4 wa = *reinterpret_cast<const float4*>(W + (size_t)(k0 + wk) * N + cb + wn);
    Xs[0][(lk + 0) * 64 + lm] = xa.x;
    Xs[0][(lk + 1) * 64 + lm] = xa.y;
    Xs[0][(lk + 2) * 64 + lm] = xa.z;
    Xs[0][(lk + 3) * 64 + lm] = xa.w;
    *reinterpret_cast<float4*>(&Ws[0][wk * 64 + wn]) = wa;
    GBAR();

    const int nt = Kc >> 4;
    int buf = 0;
    for (int t = 0; t < nt; t++) {
        float4 xn, wn4;
        const bool more = (t + 1 < nt);
        if (more) {
            int kk0 = k0 + ((t + 1) << 4);
            xn  = *reinterpret_cast<const float4*>(X + (size_t)lm * K + kk0 + lk);
            wn4 = *reinterpret_cast<const float4*>(W + (size_t)(kk0 + wk) * N + cb + wn);
        }
#pragma unroll
        for (int kk = 0; kk < 16; kk++) {
            const float4 a4 = *reinterpret_cast<const float4*>(&Xs[buf][(kk << 6) + (ty << 2)]);
            const float4 b4 = *reinterpret_cast<const float4*>(&Ws[buf][(kk << 6) + (tx << 2)]);
            const float av[4] = {a4.x, a4.y, a4.z, a4.w};
            const float bv[4] = {b4.x, b4.y, b4.z, b4.w};
#pragma unroll
            for (int i2 = 0; i2 < 4; i2++)
#pragma unroll
                for (int j2 = 0; j2 < 4; j2++)
                    acc[i2][j2] = fmaf(av[i2], bv[j2], acc[i2][j2]);
        }
        if (more) {
            const int nb = buf ^ 1;
            Xs[nb][(lk + 0) * 64 + lm] = xn.x;
            Xs[nb][(lk + 1) * 64 + lm] = xn.y;
            Xs[nb][(lk + 2) * 64 + lm] = xn.z;
            Xs[nb][(lk + 3) * 64 + lm] = xn.w;
            *reinterpret_cast<float4*>(&Ws[nb][wk * 64 + wn]) = wn4;
            buf = nb;
        }
        GBAR();
    }

    float* dst = P + (size_t)kc * 64 * N;
#pragma unroll
    for (int i = 0; i < 4; i++) {
        float4 o = make_float4(acc[i][0], acc[i][1], acc[i][2], acc[i][3]);
        *reinterpret_cast<float4*>(dst + (size_t)((ty << 2) + i) * N + cb + (tx << 2)) = o;
    }
}

// ---------------------------------------------------------------------------
// K-split reduce + bias + batch-BN (+ affine + ReLU). Extra CTAs = pure noise
// (256 thr, 8 warps x JPW jobs each).
// ---------------------------------------------------------------------------
template <bool AR, int S, int RED, int JPW>
__global__ __launch_bounds__(256) void reduce_noise(const float* __restrict__ P,
                                                    const float* __restrict__ bias,
                                                    const float* __restrict__ gamma,
                                                    const float* __restrict__ beta,
                                                    float* __restrict__ Y, int N,
                                                    int jobBase)
{
    if (blockIdx.x >= RED) {
        const int b = (int)blockIdx.x - RED;
        const int wid = threadIdx.x >> 5;
        noise_jobs(jobBase + (b * 8 + wid) * JPW, JPW);
        return;
    }

    const int c = blockIdx.x * 256 + threadIdx.x;
    const float b = bias[c];
    float s = 0.f, ss = 0.f;
#pragma unroll 4
    for (int r = 0; r < 64; r++) {
        float v = b;
#pragma unroll
        for (int q = 0; q < S; q++) v += P[((size_t)q * 64 + r) * N + c];
        s += v; ss += v * v;
    }
    const float mean = s * 0.015625f;
    const float inv  = rsqrtf(fmaf(-mean, mean, ss * 0.015625f) + 1e-5f);
    const float ga = AR ? gamma[c] : 1.0f;
    const float be = AR ? beta[c]  : 0.0f;
#pragma unroll 4
    for (int r = 0; r < 64; r++) {
        float v = b;
#pragma unroll
        for (int q = 0; q < S; q++) v += P[((size_t)q * 64 + r) * N + c];
        float y = (v - mean) * inv;
        if (AR) y = fmaxf(fmaf(y, ga, be), 0.0f);
        Y[(size_t)r * N + c] = y;
    }
}

// ---------------------------------------------------------------------------
// Iteration kernel: pure (all noise complete before this launch).
// 64 CTAs (one row each), 256 thr, 8 cols/thread.
// Depth-3 software pipeline on the noise stream: loads for iteration i+3
// issue ~3 iterations (~1000+ cyc) before use -> DRAM latency fully covered.
// ---------------------------------------------------------------------------
__device__ __forceinline__ float ex2f(float x)
{
    float y; asm("ex2.approx.f32 %0, %1;" : "=f"(y) : "f"(x)); return y;
}

__global__ __launch_bounds__(256) void iter_k(float* __restrict__ zout)
{
    const int row  = blockIdx.x;
    const int tid  = threadIdx.x;
    const int lane = tid & 31, wid = tid >> 5;
    const float C = 2.8853900817779268f;   // 2*log2(e)

    float4 ma = *(const float4*)(g_mask0 + row * 2048 + 8 * tid);
    float4 mb = *(const float4*)(g_mask0 + row * 2048 + 8 * tid + 4);
    float4 za = make_float4(0.f, 0.f, 0.f, 0.f);
    float4 zb = make_float4(0.f, 0.f, 0.f, 0.f);

    __shared__ __align__(16) float wsum[2][8];

    const float4* np = (const float4*)g_noise + (size_t)row * 512 + 2 * tid;

    // 3-deep pipeline: hold iterations i, i+1, i+2 in registers
    float4 a0 = np[0],                   b0 = np[1];
    float4 a1 = np[(size_t)1 * 32768],   b1 = np[(size_t)1 * 32768 + 1];
    float4 a2 = np[(size_t)2 * 32768],   b2 = np[(size_t)2 * 32768 + 1];

    for (int i = 0; i < 1024; i++) {
        const float e0 = ex2f(fmaf(ma.x, C, a0.x));
        const float e1 = ex2f(fmaf(ma.y, C, a0.y));
        const float e2 = ex2f(fmaf(ma.z, C, a0.z));
        const float e3 = ex2f(fmaf(ma.w, C, a0.w));
        const float e4 = ex2f(fmaf(mb.x, C, b0.x));
        const float e5 = ex2f(fmaf(mb.y, C, b0.y));
        const float e6 = ex2f(fmaf(mb.z, C, b0.z));
        const float e7 = ex2f(fmaf(mb.w, C, b0.w));

        // rotate pipeline and issue iteration i+3's loads NOW (used in ~3 iters)
        a0 = a1; b0 = b1;
        a1 = a2; b1 = b2;
        if (i + 3 < 1024) {
            a2 = np[(size_t)(i + 3) * 32768];
            b2 = np[(size_t)(i + 3) * 32768 + 1];
        }

        float s = ((e0 + e1) + (e2 + e3)) + ((e4 + e5) + (e6 + e7));
#pragma unroll
        for (int o = 16; o; o >>= 1) s += __shfl_xor_sync(0xffffffffu, s, o);
        if (lane == 0) wsum[i & 1][wid] = s;
        __syncthreads();

        const float4* wp = (const float4*)wsum[i & 1];
        const float4 t0 = wp[0], t1 = wp[1];
        const float tt = ((t0.x + t0.y) + (t0.z + t0.w)) + ((t1.x + t1.y) + (t1.z + t1.w));
        float r; asm("rcp.approx.f32 %0, %1;" : "=f"(r) : "f"(tt));
        ma.x = e0 * r; ma.y = e1 * r; ma.z = e2 * r; ma.w = e3 * r;
        mb.x = e4 * r; mb.y = e5 * r; mb.z = e6 * r; mb.w = e7 * r;
        za.x = fmaxf(za.x, ma.x); za.y = fmaxf(za.y, ma.y);
        za.z = fmaxf(za.z, ma.z); za.w = fmaxf(za.w, ma.w);
        zb.x = fmaxf(zb.x, mb.x); zb.y = fmaxf(zb.y, mb.y);
        zb.z = fmaxf(zb.z, mb.z); zb.w = fmaxf(zb.w, mb.w);
    }
    *(float4*)(zout + row * 2048 + 8 * tid)     = za;
    *(float4*)(zout + row * 2048 + 8 * tid + 4) = zb;
}

// ---------------------------------------------------------------------------
// Launch. Job budget (512-elem warp-jobs), 262144 total, iteration-ordered:
//   g1: 512 CTAs x 8 warps x  8 =  32768  @0        (iters   0..127)
//   r1: 1024 noise CTAs x 8 x 4 =  32768  @32768    (iters 128..255)
//   g2: 1024 CTAs x 8 x 16     = 131072  @65536    (iters 256..767)
//   r2: 512 x 8 x 4            =  16384  @196608   (iters 768..831)
//   g3: 256 x 8 x 16           =  32768  @212992   (iters 832..959)
//   r3: 512 x 8 x 4            =  16384  @245760   (iters 960..1023)
// ---------------------------------------------------------------------------
extern "C" void kernel_launch(void* const* d_in, const int* in_sizes, int n_in,
                              void* d_out, int out_size)
{
    const float* f   = (const float*)d_in[0];
    const float* W1  = (const float*)d_in[1];
    const float* b1  = (const float*)d_in[2];
    const float* g1  = (const float*)d_in[3];
    const float* be1 = (const float*)d_in[4];
    const float* W2  = (const float*)d_in[5];
    const float* b2  = (const float*)d_in[6];
    const float* g2  = (const float*)d_in[7];
    const float* be2 = (const float*)d_in[8];
    const float* W3  = (const float*)d_in[9];
    const float* b3  = (const float*)d_in[10];
    float* out = (float*)d_out;

    void *p1, *p2, *p3, *pp, *pp3;
    cudaGetSymbolAddress(&p1, g_h1);
    cudaGetSymbolAddress(&p2, g_h2);
    cudaGetSymbolAddress(&p3, g_mask0);
    cudaGetSymbolAddress(&pp, g_p);
    cudaGetSymbolAddress(&pp3, g_p3);
    float* h1 = (float*)p1;
    float* h2 = (float*)p2;
    float* mk = (float*)p3;
    float* P  = (float*)pp;
    float* P3 = (float*)pp3;

    keys_kernel<<<1, 1024>>>();

    gemm_noise<128, 4, 8><<<512, 512>>>(f,  W1, P, 2048, 8192, 0);
    reduce_noise<true, 4, 32, 4><<<32 + 1024, 256>>>(P, b1, g1, be1, h1, 8192, 32768);

    gemm_noise<128, 8, 16><<<1024, 512>>>(h1, W2, P, 8192, 8192, 65536);
    reduce_noise<true, 8, 32, 4><<<32 + 512, 256>>>(P, b2, g2, be2, h2, 8192, 196608);

    gemm_noise<32, 8, 16><<<256, 512>>>(h2, W3, P3, 8192, 2048, 212992);
    reduce_noise<false, 8, 8, 4><<<8 + 512, 256>>>(P3, b3, nullptr, nullptr, mk, 2048, 245760);

    iter_k<<<64, 256>>>(out);
}